// round 1
// baseline (speedup 1.0000x reference)
#include <cuda_runtime.h>
#include <math.h>

// Problem constants (fixed by the dataset)
#define Bq   2
#define Nc   6
#define Cc   256
#define Mq   900
#define EPSF 1e-5f

// Per-level H, W
#define H0 116
#define W0 200
#define H1 58
#define W1 100
#define H2 29
#define W2 50
#define H3 15
#define W3 25

// Bilinear gather of one channel at (x0, y0)..(x0+1, y0+1) with per-corner
// zero-padding, matching jax grid_sample(align_corners=False, padding=zeros).
// Bounds are evaluated in float so NaN / huge coords safely produce 0.
template <int H, int W>
__device__ __forceinline__ float samp_level(const float* __restrict__ f,
                                            int bn, int c,
                                            float x0f, float y0f,
                                            float w00, float w10,
                                            float w01, float w11)
{
    // corner validity (x1 = x0+1, y1 = y0+1)
    bool bx0 = (x0f >= 0.0f)  && (x0f <= (float)(W - 1));
    bool bx1 = (x0f >= -1.0f) && (x0f <= (float)(W - 2));
    bool by0 = (y0f >= 0.0f)  && (y0f <= (float)(H - 1));
    bool by1 = (y0f >= -1.0f) && (y0f <= (float)(H - 2));
    if (!((bx0 | bx1) & (by0 | by1))) return 0.0f;

    // safe int conversion (coords are bounded by the checks above whenever used)
    float xc = fmaxf(fminf(x0f, 1.0e8f), -1.0e8f);
    float yc = fmaxf(fminf(y0f, 1.0e8f), -1.0e8f);
    int xi = (int)xc;
    int yi = (int)yc;

    const float* base = f + ((long long)(bn * Cc + c)) * (H * W);
    const float* row0 = base + yi * W;
    const float* row1 = row0 + W;

    float v = 0.0f;
    // predicated loads — compiler emits @P LDG, keeping all 4 in flight
    if (by0 & bx0) v += w00 * __ldg(row0 + xi);
    if (by0 & bx1) v += w10 * __ldg(row0 + xi + 1);
    if (by1 & bx0) v += w01 * __ldg(row1 + xi);
    if (by1 & bx1) v += w11 * __ldg(row1 + xi + 1);
    return v;
}

__global__ void __launch_bounds__(Cc)
feature_sampler_kernel(const float* __restrict__ f0,
                       const float* __restrict__ f1,
                       const float* __restrict__ f2,
                       const float* __restrict__ f3,
                       const float* __restrict__ refp,   // (B, M, 3)
                       const float* __restrict__ l2i,    // (B, N, 4, 4)
                       float* __restrict__ out)          // (B, M, C)
{
    int bm = blockIdx.x;           // 0 .. B*M-1
    int b  = bm / Mq;
    int m  = bm - b * Mq;
    int c  = threadIdx.x;          // channel

    // denormalized reference point (broadcast loads)
    const float* rp = refp + (b * Mq + m) * 3;
    float rx = rp[0] * 122.4f - 61.2f;
    float ry = rp[1] * 122.4f - 61.2f;
    float rz = rp[2] * 20.0f  - 10.0f;

    float acc = 0.0f;
    float cnt = 0.0f;

    #pragma unroll
    for (int n = 0; n < Nc; n++) {
        const float* Mt = l2i + (b * Nc + n) * 16;
        float c0 = Mt[0] * rx + Mt[1] * ry + Mt[2]  * rz + Mt[3];
        float c1 = Mt[4] * rx + Mt[5] * ry + Mt[6]  * rz + Mt[7];
        float c2 = Mt[8] * rx + Mt[9] * ry + Mt[10] * rz + Mt[11];

        if (!(c2 > EPSF)) continue;   // mask kills this camera's contribution
        cnt += 1.0f;

        float zd = c2 + EPSF;
        float px = c0 / zd;
        float py = c1 / zd;

        // normalization cancels: pixel coord is px-0.5 for EVERY level
        float x = px - 0.5f;
        float y = py - 0.5f;
        float x0f = floorf(x);
        float y0f = floorf(y);
        float wx1 = x - x0f, wx0 = 1.0f - wx1;
        float wy1 = y - y0f, wy0 = 1.0f - wy1;
        float w00 = wx0 * wy0, w10 = wx1 * wy0;
        float w01 = wx0 * wy1, w11 = wx1 * wy1;

        int bn = b * Nc + n;
        float s = 0.0f;
        s += samp_level<H0, W0>(f0, bn, c, x0f, y0f, w00, w10, w01, w11);
        s += samp_level<H1, W1>(f1, bn, c, x0f, y0f, w00, w10, w01, w11);
        s += samp_level<H2, W2>(f2, bn, c, x0f, y0f, w00, w10, w01, w11);
        s += samp_level<H3, W3>(f3, bn, c, x0f, y0f, w00, w10, w01, w11);

        acc += 0.25f * s;
    }

    out[(b * Mq + m) * Cc + c] = acc / (cnt + EPSF);
}

extern "C" void kernel_launch(void* const* d_in, const int* in_sizes, int n_in,
                              void* d_out, int out_size)
{
    const float* f0   = (const float*)d_in[0];
    const float* f1   = (const float*)d_in[1];
    const float* f2   = (const float*)d_in[2];
    const float* f3   = (const float*)d_in[3];
    const float* refp = (const float*)d_in[4];
    const float* l2i  = (const float*)d_in[5];
    float* out = (float*)d_out;

    feature_sampler_kernel<<<Bq * Mq, Cc>>>(f0, f1, f2, f3, refp, l2i, out);
}

// round 2
// speedup vs baseline: 1.0082x; 1.0082x over previous
#include <cuda_runtime.h>
#include <math.h>

// Problem constants (fixed by the dataset)
#define Bq   2
#define Nc   6
#define Cc   256
#define Mq   900
#define EPSF 1e-5f

// Per-level H, W
#define H0 116
#define W0 200
#define H1 58
#define W1 100
#define H2 29
#define W2 50
#define H3 15
#define W3 25

#define THREADS 128   // each thread handles channels c and c+128

// Bilinear gather for TWO channels (c, c+128) at the 4 corners, fully
// predicated (no branches) so ptxas can batch all loads of a camera.
// zv = camera z-validity predicate (warp-uniform).
template <int H, int W>
__device__ __forceinline__ void samp2(const float* __restrict__ f,
                                      int bn, int c, bool zv,
                                      float x0f, float y0f,
                                      float w00, float w10,
                                      float w01, float w11,
                                      float& a0, float& a1)
{
    bool bx0 = (x0f >= 0.0f)  & (x0f <= (float)(W - 1));
    bool bx1 = (x0f >= -1.0f) & (x0f <= (float)(W - 2));
    bool by0 = (y0f >= 0.0f)  & (y0f <= (float)(H - 1));
    bool by1 = (y0f >= -1.0f) & (y0f <= (float)(H - 2));

    // safe int conversion (CUDA float->int saturates; clamp anyway)
    int xi = (int)fmaxf(fminf(x0f, 1.0e8f), -1.0e8f);
    int yi = (int)fmaxf(fminf(y0f, 1.0e8f), -1.0e8f);

    const float* p0 = f + ((long long)(bn * Cc + c)) * (H * W) + yi * W + xi;
    const float* p1 = p0 + (long long)(THREADS) * (H * W);   // channel c+128

    bool q00 = zv & by0 & bx0;
    bool q10 = zv & by0 & bx1;
    bool q01 = zv & by1 & bx0;
    bool q11 = zv & by1 & bx1;

    // predicated loads — never execute when predicate is false
    if (q00) { a0 += w00 * __ldg(p0);         a1 += w00 * __ldg(p1);         }
    if (q10) { a0 += w10 * __ldg(p0 + 1);     a1 += w10 * __ldg(p1 + 1);     }
    if (q01) { a0 += w01 * __ldg(p0 + W);     a1 += w01 * __ldg(p1 + W);     }
    if (q11) { a0 += w11 * __ldg(p0 + W + 1); a1 += w11 * __ldg(p1 + W + 1); }
}

__global__ void __launch_bounds__(THREADS)
feature_sampler_kernel(const float* __restrict__ f0,
                       const float* __restrict__ f1,
                       const float* __restrict__ f2,
                       const float* __restrict__ f3,
                       const float* __restrict__ refp,   // (B, M, 3)
                       const float* __restrict__ l2i,    // (B, N, 4, 4)
                       float* __restrict__ out)          // (B, M, C)
{
    int bm = blockIdx.x;           // 0 .. B*M-1
    int b  = bm / Mq;
    int m  = bm - b * Mq;
    int c  = threadIdx.x;          // channel (also handles c+128)

    const float* rp = refp + (b * Mq + m) * 3;
    float rx = rp[0] * 122.4f - 61.2f;
    float ry = rp[1] * 122.4f - 61.2f;
    float rz = rp[2] * 20.0f  - 10.0f;

    float acc0 = 0.0f, acc1 = 0.0f;
    float cnt = 0.0f;

    #pragma unroll
    for (int n = 0; n < Nc; n++) {
        const float* Mt = l2i + (b * Nc + n) * 16;
        float c0 = Mt[0] * rx + Mt[1] * ry + Mt[2]  * rz + Mt[3];
        float c1 = Mt[4] * rx + Mt[5] * ry + Mt[6]  * rz + Mt[7];
        float c2 = Mt[8] * rx + Mt[9] * ry + Mt[10] * rz + Mt[11];

        bool zv = (c2 > EPSF);
        cnt += zv ? 1.0f : 0.0f;

        float zd = c2 + EPSF;
        float rcp = __fdividef(1.0f, zd);
        float px = c0 * rcp;
        float py = c1 * rcp;

        // grid-sample normalization cancels: pixel coord = px - 0.5 at EVERY level
        float x = px - 0.5f;
        float y = py - 0.5f;
        float x0f = floorf(x);
        float y0f = floorf(y);
        float wx1 = x - x0f, wx0 = 1.0f - wx1;
        float wy1 = y - y0f, wy0 = 1.0f - wy1;
        float w00 = wx0 * wy0, w10 = wx1 * wy0;
        float w01 = wx0 * wy1, w11 = wx1 * wy1;

        int bn = b * Nc + n;
        float s0 = 0.0f, s1 = 0.0f;
        samp2<H0, W0>(f0, bn, c, zv, x0f, y0f, w00, w10, w01, w11, s0, s1);
        samp2<H1, W1>(f1, bn, c, zv, x0f, y0f, w00, w10, w01, w11, s0, s1);
        samp2<H2, W2>(f2, bn, c, zv, x0f, y0f, w00, w10, w01, w11, s0, s1);
        samp2<H3, W3>(f3, bn, c, zv, x0f, y0f, w00, w10, w01, w11, s0, s1);

        acc0 += 0.25f * s0;
        acc1 += 0.25f * s1;
    }

    float inv = __fdividef(1.0f, cnt + EPSF);
    float* o = out + (b * Mq + m) * Cc;
    o[c]           = acc0 * inv;
    o[c + THREADS] = acc1 * inv;
}

extern "C" void kernel_launch(void* const* d_in, const int* in_sizes, int n_in,
                              void* d_out, int out_size)
{
    const float* f0   = (const float*)d_in[0];
    const float* f1   = (const float*)d_in[1];
    const float* f2   = (const float*)d_in[2];
    const float* f3   = (const float*)d_in[3];
    const float* refp = (const float*)d_in[4];
    const float* l2i  = (const float*)d_in[5];
    float* out = (float*)d_out;

    feature_sampler_kernel<<<Bq * Mq, THREADS>>>(f0, f1, f2, f3, refp, l2i, out);
}